// round 3
// baseline (speedup 1.0000x reference)
#include <cuda_runtime.h>

typedef unsigned long long ull;
#define FULLM 0xffffffffu

// ---------------- device scratch (no allocations allowed) ----------------
__device__ int   g_order[1024];   // batch ids sorted by len descending
__device__ float g_res[512];      // per-warp (pair) partial results

// ---------------- f32x2 helpers (sm_103a packed fp32 path) ---------------
__device__ __forceinline__ ull pk2(float lo, float hi) {
    ull r; asm("mov.b64 %0,{%1,%2};" : "=l"(r) : "f"(lo), "f"(hi)); return r;
}
__device__ __forceinline__ float2 upk2(ull v) {
    float2 f; asm("mov.b64 {%0,%1},%2;" : "=f"(f.x), "=f"(f.y) : "l"(v)); return f;
}
__device__ __forceinline__ ull ffma2(ull a, ull b, ull c) {
    ull d; asm("fma.rn.f32x2 %0,%1,%2,%3;" : "=l"(d) : "l"(a), "l"(b), "l"(c)); return d;
}
__device__ __forceinline__ float rcpa(float x) {
    float r; asm("rcp.approx.f32 %0,%1;" : "=f"(r) : "f"(x)); return r;
}

// ---------------- prep: rank batches by length (desc), O(B^2) trivial ----
__global__ void prep_kernel(const int* __restrict__ lens) {
    __shared__ int sl[1024];
    int b = threadIdx.x;
    sl[b] = lens[b];
    __syncthreads();
    int len = sl[b];
    int rank = 0;
#pragma unroll 8
    for (int i = 0; i < 1024; i++) {
        int li = sl[i];
        rank += (li > len) || ((li == len) && (i < b));
    }
    g_order[rank] = b;
}

// ---------------- main CRF kernel ----------------------------------------
// 128 blocks x 128 threads. warp gw handles batches order[gw] (long, "A")
// and order[1023-gw] (short, "B"), interleaved per timestep.
// State: v (unnormalized alpha in linear domain, in shared, double-buffered),
// M (log offset), deferred 1/max normalization.
__global__ __launch_bounds__(128, 1) void crf_kernel(
    const float* __restrict__ logits,   // [1024,512,50]
    const float* __restrict__ tr,       // [50,50]
    const int*   __restrict__ labels,   // [1024,512]
    const int*   __restrict__ lens)     // [1024]
{
    __shared__ __align__(16) float vbuf[4][2][2][64]; // [warp][batch][dblbuf][state]

    const int lane = threadIdx.x & 31;
    const int warp = threadIdx.x >> 5;
    const int gw   = blockIdx.x * 4 + warp;

    const int bA = g_order[gw];
    const int bB = g_order[1023 - gw];
    const int lenA = lens[bA];
    const int lenB = lens[bB];          // lenB <= lenA by construction

    const int  j0 = 2 * lane;           // this lane owns states j0, j0+1
    const bool vl = (lane < 25);        // states 0..49 real; lanes 25..31 padding

    // ---- build E = exp(transitions) rows for this lane's 2 states -------
    ull E0[25], E1[25];
#pragma unroll
    for (int k = 0; k < 25; k++) {
        float e00 = 0.f, e01 = 0.f, e10 = 0.f, e11 = 0.f;
        if (vl) {
            float2 r0 = *(const float2*)&tr[ j0      * 50 + 2 * k];
            float2 r1 = *(const float2*)&tr[(j0 + 1) * 50 + 2 * k];
            e00 = __expf(r0.x); e01 = __expf(r0.y);
            e10 = __expf(r1.x); e11 = __expf(r1.y);
        }
        E0[k] = pk2(e00, e01);
        E1[k] = pk2(e10, e11);
    }
    const float Es0 = vl ? __expf(tr[49 * 50 + j0])     : 0.f;  // exp(trans[stop, j])
    const float Es1 = vl ? __expf(tr[49 * 50 + j0 + 1]) : 0.f;

    // ---- init v buffers: onehot(start=48) ------------------------------
#pragma unroll
    for (int X = 0; X < 2; X++) {
        vbuf[warp][X][0][lane] = 0.f; vbuf[warp][X][0][lane + 32] = 0.f;
        vbuf[warp][X][1][lane] = 0.f; vbuf[warp][X][1][lane + 32] = 0.f;
    }
    __syncwarp();
    if (lane == 24) { vbuf[warp][0][0][48] = 1.f; vbuf[warp][1][0][48] = 1.f; }
    __syncwarp();

    // ---- per-batch running state ---------------------------------------
    const float NEGBIG = -1e30f;
    float MA = 0.f, MB = 0.f, invrA = 1.f, invrB = 1.f, logrA = 0.f, logrB = 0.f;
    float emA = 0.f, emB = 0.f, trnA = 0.f, trnB = 0.f;
    int   prevA = 48, prevB = 48;
    float uA0 = 0.f, uA1 = 0.f, uB0 = 0.f, uB1 = 0.f;

    const int baseA = bA * 512;
    const int baseB = bB * 512;

    float2 lgA = make_float2(NEGBIG, NEGBIG), lgB = lgA;
    if (vl) lgA = *(const float2*)&logits[baseA * 50 + j0];
    if (vl) lgB = *(const float2*)&logits[baseB * 50 + j0];
    int labA = __ldg(&labels[baseA]);
    int labB = __ldg(&labels[baseB]);

    // one forward step for one batch (fully inlined; E0/E1 captured)
    auto stepX = [&](int tt, const float* vcur, float* vnxt,
                     float& M, float& invr, float& logr,
                     float& em, float& trn, int& prev,
                     float2& lg, int& lab, float& u0, float& u1,
                     int base, int len) {
        M += logr;                                  // apply previous step's rescale
        const float px = __expf(lg.x) * invr;
        const float py = __expf(lg.y) * invr;

        // emission + transition score gathers (uniform, off critical path)
        const float cand = (lab & 1) ? lg.y : lg.x;
        em += __shfl_sync(FULLM, cand, lab >> 1);
        trn += __ldg(&tr[lab * 50 + prev]);
        prev = lab;

        // prefetch next timestep (clamped, branch-free)
        const int tn = (tt + 1 < len) ? tt + 1 : len - 1;
        float2 lgn = make_float2(NEGBIG, NEGBIG);
        if (vl) lgn = *(const float2*)&logits[(base + tn) * 50 + j0];
        const int labn = __ldg(&labels[base + tn]);

        // matvec: Sigma_j = sum_i E[j,i] * v[i]  (packed f32x2, 4 acc chains)
        const ulonglong2* vs = (const ulonglong2*)vcur;
        ull a0 = pk2(0.f, 0.f), b0 = a0, a1 = a0, b1 = a0;
#pragma unroll
        for (int k = 0; k < 12; k++) {
            ulonglong2 vv = vs[k];
            a0 = ffma2(E0[2 * k],     vv.x, a0);
            b0 = ffma2(E0[2 * k + 1], vv.y, b0);
            a1 = ffma2(E1[2 * k],     vv.x, a1);
            b1 = ffma2(E1[2 * k + 1], vv.y, b1);
        }
        {   // tail pair: states i = 48,49
            ull vt = *(const ull*)&vcur[48];
            a0 = ffma2(E0[24], vt, a0);
            a1 = ffma2(E1[24], vt, a1);
        }
        float2 s0 = upk2(a0), s0b = upk2(b0), s1 = upk2(a1), s1b = upk2(b1);
        const float S0 = (s0.x + s0.y) + (s0b.x + s0b.y);
        const float S1 = (s1.x + s1.y) + (s1b.x + s1b.y);

        u0 = S0 * px;
        u1 = S1 * py;
        if (vl) *(float2*)&vnxt[j0] = make_float2(u0, u1);

        // deferred normalization: max over warp, consumed next step
        float m = fmaxf(u0, u1);
        m = fmaxf(m, __shfl_xor_sync(FULLM, m, 16));
        m = fmaxf(m, __shfl_xor_sync(FULLM, m, 8));
        m = fmaxf(m, __shfl_xor_sync(FULLM, m, 4));
        m = fmaxf(m, __shfl_xor_sync(FULLM, m, 2));
        m = fmaxf(m, __shfl_xor_sync(FULLM, m, 1));
        invr = rcpa(m);
        logr = __logf(m);

        lg = lgn;
        lab = labn;
    };

    int t = 0;
    // ---- phase 1: both batches interleaved (latency hiding) ------------
    for (; t < lenB; ++t) {
        const int cur = t & 1;
        stepX(t, &vbuf[warp][0][cur][0], &vbuf[warp][0][cur ^ 1][0],
              MA, invrA, logrA, emA, trnA, prevA, lgA, labA, uA0, uA1, baseA, lenA);
        stepX(t, &vbuf[warp][1][cur][0], &vbuf[warp][1][cur ^ 1][0],
              MB, invrB, logrB, emB, trnB, prevB, lgB, labB, uB0, uB1, baseB, lenB);
        __syncwarp();
    }
    // ---- finalize B -----------------------------------------------------
    float resB;
    {
        trnB += __ldg(&tr[49 * 50 + prevB]);
        float w = uB0 * Es0 + uB1 * Es1;
        w += __shfl_xor_sync(FULLM, w, 16);
        w += __shfl_xor_sync(FULLM, w, 8);
        w += __shfl_xor_sync(FULLM, w, 4);
        w += __shfl_xor_sync(FULLM, w, 2);
        w += __shfl_xor_sync(FULLM, w, 1);
        resB = (MB + __logf(w)) - emB - trnB;
    }
    // ---- phase 2: remaining steps of the long batch ---------------------
    for (; t < lenA; ++t) {
        const int cur = t & 1;
        stepX(t, &vbuf[warp][0][cur][0], &vbuf[warp][0][cur ^ 1][0],
              MA, invrA, logrA, emA, trnA, prevA, lgA, labA, uA0, uA1, baseA, lenA);
        __syncwarp();
    }
    // ---- finalize A -----------------------------------------------------
    float resA;
    {
        trnA += __ldg(&tr[49 * 50 + prevA]);
        float w = uA0 * Es0 + uA1 * Es1;
        w += __shfl_xor_sync(FULLM, w, 16);
        w += __shfl_xor_sync(FULLM, w, 8);
        w += __shfl_xor_sync(FULLM, w, 4);
        w += __shfl_xor_sync(FULLM, w, 2);
        w += __shfl_xor_sync(FULLM, w, 1);
        resA = (MA + __logf(w)) - emA - trnA;
    }

    if (lane == 0) g_res[gw] = resA + resB;
}

// ---------------- deterministic final reduction ---------------------------
__global__ void reduce_kernel(float* __restrict__ out) {
    __shared__ float s[512];
    int i = threadIdx.x;
    s[i] = g_res[i];
    __syncthreads();
    for (int off = 256; off > 0; off >>= 1) {
        if (i < off) s[i] += s[i + off];
        __syncthreads();
    }
    if (i == 0) *out = s[0] * (1.0f / 1024.0f);
}

// ---------------- launch ---------------------------------------------------
extern "C" void kernel_launch(void* const* d_in, const int* in_sizes, int n_in,
                              void* d_out, int out_size) {
    const float* logits = (const float*)d_in[0];
    const float* trans  = (const float*)d_in[1];
    const int*   labels = (const int*)d_in[2];
    const int*   lens   = (const int*)d_in[3];
    float*       out    = (float*)d_out;

    prep_kernel<<<1, 1024>>>(lens);
    crf_kernel<<<128, 128>>>(logits, trans, labels, lens);
    reduce_kernel<<<1, 512>>>(out);
}

// round 6
// speedup vs baseline: 1.3289x; 1.3289x over previous
#include <cuda_runtime.h>

typedef unsigned long long ull;
#define FULLM 0xffffffffu

// ---------------- device scratch (no allocations allowed) ----------------
__device__ int   g_order[1024];   // batch ids sorted by len descending
__device__ float g_res[1024];     // per-batch results (indexed by rank)

// ---------------- f32x2 helpers (sm_103a packed fp32 path) ---------------
__device__ __forceinline__ ull pk2(float lo, float hi) {
    ull r; asm("mov.b64 %0,{%1,%2};" : "=l"(r) : "f"(lo), "f"(hi)); return r;
}
__device__ __forceinline__ float2 upk2(ull v) {
    float2 f; asm("mov.b64 {%0,%1},%2;" : "=f"(f.x), "=f"(f.y) : "l"(v)); return f;
}
__device__ __forceinline__ ull ffma2(ull a, ull b, ull c) {
    ull d; asm("fma.rn.f32x2 %0,%1,%2,%3;" : "=l"(d) : "l"(a), "l"(b), "l"(c)); return d;
}

// ---------------- prep: rank batches by length (desc) --------------------
// 1024 blocks x 32 threads: block b computes rank of batch b via lane-parallel
// scan + warp reduction. ~2us total (vs 32us single-block version).
__global__ void prep_kernel(const int* __restrict__ lens) {
    const int b    = blockIdx.x;
    const int lane = threadIdx.x;
    const int len  = __ldg(&lens[b]);
    int rank = 0;
#pragma unroll
    for (int k = 0; k < 32; k++) {
        const int i  = k * 32 + lane;
        const int li = __ldg(&lens[i]);
        rank += (li > len) || ((li == len) && (i < b));
    }
    rank += __shfl_xor_sync(FULLM, rank, 16);
    rank += __shfl_xor_sync(FULLM, rank, 8);
    rank += __shfl_xor_sync(FULLM, rank, 4);
    rank += __shfl_xor_sync(FULLM, rank, 2);
    rank += __shfl_xor_sync(FULLM, rank, 1);
    if (lane == 0) g_order[rank] = b;
}

// ---------------- main CRF kernel ----------------------------------------
// 128 blocks x 256 threads (8 warps). Each warp owns ONE batch.
// Warps w and w+4 share SMSP (w&3): one gets rank r=blk*4+(w&3) (long),
// the other rank 1023-r (short) -> per-SMSP work ~ 513 steps, arbiter
// interleaves the two warps to hide per-step latency.
// State v = unnormalized linear-domain alpha (smem, double-buffered),
// log-offset M, per-step normalizer = lane0 broadcast (cheap, exact via M).
__global__ __launch_bounds__(256, 1) void crf_kernel(
    const float* __restrict__ logits,   // [1024,512,50]
    const float* __restrict__ tr,       // [50,50]
    const int*   __restrict__ labels,   // [1024,512]
    const int*   __restrict__ lens)     // [1024]
{
    __shared__ __align__(16) float vbuf[8][2][64]; // [warp][dblbuf][state]

    const int lane = threadIdx.x & 31;
    const int warp = threadIdx.x >> 5;

    const int r  = blockIdx.x * 4 + (warp & 3);   // rank in [0,512)
    const int gw = (warp < 4) ? r : (1023 - r);   // this warp's rank
    const int b  = g_order[gw];
    const int len  = lens[b];
    const int base = b * 512;

    const int  j0 = 2 * lane;            // this lane owns states j0, j0+1
    const bool vl = (lane < 25);         // states 0..49 real; rest padding

    // ---- E = exp(transitions) rows for this lane's 2 states (regs) -----
    ull E0[25], E1[25];
#pragma unroll
    for (int k = 0; k < 25; k++) {
        float e00 = 0.f, e01 = 0.f, e10 = 0.f, e11 = 0.f;
        if (vl) {
            float2 r0 = *(const float2*)&tr[ j0      * 50 + 2 * k];
            float2 r1 = *(const float2*)&tr[(j0 + 1) * 50 + 2 * k];
            e00 = __expf(r0.x); e01 = __expf(r0.y);
            e10 = __expf(r1.x); e11 = __expf(r1.y);
        }
        E0[k] = pk2(e00, e01);
        E1[k] = pk2(e10, e11);
    }
    const float Es0 = vl ? __expf(tr[49 * 50 + j0])     : 0.f; // exp(tr[stop,j])
    const float Es1 = vl ? __expf(tr[49 * 50 + j0 + 1]) : 0.f;

    // ---- init v: onehot(start=48) in buffer 0 ---------------------------
    vbuf[warp][0][lane] = 0.f; vbuf[warp][0][lane + 32] = 0.f;
    vbuf[warp][1][lane] = 0.f; vbuf[warp][1][lane + 32] = 0.f;
    __syncwarp();
    if (lane == 24) vbuf[warp][0][48] = 1.f;
    __syncwarp();

    // ---- running state ---------------------------------------------------
    const float NEGBIG = -1e30f;
    float M = 0.f, logr = 0.f;           // logr = log(normalizer of prev step)
    float em = 0.f, trn = 0.f;
    int   prev = 48;
    float u0 = 0.f, u1 = 0.f;

    float2 lg = make_float2(NEGBIG, NEGBIG);
    if (vl) lg = *(const float2*)&logits[base * 50 + j0];
    int lab = __ldg(&labels[base]);

    for (int t = 0; t < len; ++t) {
        M += logr;                                   // fold prev normalizer
        const float px = __expf(lg.x - logr);        // exp(logit)/m_prev
        const float py = __expf(lg.y - logr);

        // emission + transition score gathers (off critical path)
        const float cand = (lab & 1) ? lg.y : lg.x;
        em += __shfl_sync(FULLM, cand, lab >> 1);
        trn += __ldg(&tr[lab * 50 + prev]);
        prev = lab;

        // prefetch next timestep (clamped, branch-free)
        const int tn = (t + 1 < len) ? t + 1 : len - 1;
        float2 lgn = make_float2(NEGBIG, NEGBIG);
        if (vl) lgn = *(const float2*)&logits[(base + tn) * 50 + j0];
        const int labn = __ldg(&labels[base + tn]);

        // matvec: S_j = sum_i E[j,i] * v[i]  (packed f32x2, 4 acc chains)
        const int cur = t & 1;
        const ulonglong2* vs = (const ulonglong2*)&vbuf[warp][cur][0];
        ull a0 = pk2(0.f, 0.f), b0 = a0, a1 = a0, b1 = a0;
#pragma unroll
        for (int k = 0; k < 12; k++) {
            ulonglong2 vv = vs[k];
            a0 = ffma2(E0[2 * k],     vv.x, a0);
            b0 = ffma2(E0[2 * k + 1], vv.y, b0);
            a1 = ffma2(E1[2 * k],     vv.x, a1);
            b1 = ffma2(E1[2 * k + 1], vv.y, b1);
        }
        {   // tail pair: states 48,49
            ull vt = *(const ull*)&vbuf[warp][cur][48];
            a0 = ffma2(E0[24], vt, a0);
            a1 = ffma2(E1[24], vt, a1);
        }
        float2 s0 = upk2(a0), s0b = upk2(b0), s1 = upk2(a1), s1b = upk2(b1);
        const float S0 = (s0.x + s0.y) + (s0b.x + s0b.y);
        const float S1 = (s1.x + s1.y) + (s1b.x + s1b.y);

        u0 = S0 * px;
        u1 = S1 * py;
        if (vl) *(float2*)&vbuf[warp][cur ^ 1][j0] = make_float2(u0, u1);

        // cheap normalizer: lane0's local max, broadcast (1 shfl).
        // Exactness preserved via M; fp32 range headroom >> state spread.
        float m = fmaxf(u0, u1);
        m = __shfl_sync(FULLM, m, 0);
        logr = __logf(m);

        lg = lgn;
        lab = labn;
        __syncwarp();
    }

    // ---- finalize --------------------------------------------------------
    trn += __ldg(&tr[49 * 50 + prev]);
    float w = u0 * Es0 + u1 * Es1;
    w += __shfl_xor_sync(FULLM, w, 16);
    w += __shfl_xor_sync(FULLM, w, 8);
    w += __shfl_xor_sync(FULLM, w, 4);
    w += __shfl_xor_sync(FULLM, w, 2);
    w += __shfl_xor_sync(FULLM, w, 1);
    const float res = (M + __logf(w)) - em - trn;

    if (lane == 0) g_res[gw] = res;
}

// ---------------- deterministic final reduction ---------------------------
__global__ void reduce_kernel(float* __restrict__ out) {
    __shared__ float s[512];
    int i = threadIdx.x;
    s[i] = g_res[i] + g_res[i + 512];
    __syncthreads();
    for (int off = 256; off > 0; off >>= 1) {
        if (i < off) s[i] += s[i + off];
        __syncthreads();
    }
    if (i == 0) *out = s[0] * (1.0f / 1024.0f);
}

// ---------------- launch ---------------------------------------------------
extern "C" void kernel_launch(void* const* d_in, const int* in_sizes, int n_in,
                              void* d_out, int out_size) {
    const float* logits = (const float*)d_in[0];
    const float* trans  = (const float*)d_in[1];
    const int*   labels = (const int*)d_in[2];
    const int*   lens   = (const int*)d_in[3];
    float*       out    = (float*)d_out;

    prep_kernel<<<1024, 32>>>(lens);
    crf_kernel<<<128, 256>>>(logits, trans, labels, lens);
    reduce_kernel<<<1, 512>>>(out);
}

// round 7
// speedup vs baseline: 1.4636x; 1.1014x over previous
#include <cuda_runtime.h>

typedef unsigned long long ull;
#define FULLM 0xffffffffu

// ---------------- device scratch (no allocations allowed) ----------------
__device__ int   g_order[1024];   // batch ids sorted by len descending
__device__ float g_res[1024];     // per-batch results (indexed by rank)

// ---------------- f32x2 helpers (sm_103a packed fp32 path) ---------------
__device__ __forceinline__ ull pk2(float lo, float hi) {
    ull r; asm("mov.b64 %0,{%1,%2};" : "=l"(r) : "f"(lo), "f"(hi)); return r;
}
__device__ __forceinline__ float2 upk2(ull v) {
    float2 f; asm("mov.b64 {%0,%1},%2;" : "=f"(f.x), "=f"(f.y) : "l"(v)); return f;
}
__device__ __forceinline__ ull ffma2(ull a, ull b, ull c) {
    ull d; asm("fma.rn.f32x2 %0,%1,%2,%3;" : "=l"(d) : "l"(a), "l"(b), "l"(c)); return d;
}

// ---------------- prep: rank batches by length (desc) --------------------
// 128 blocks x 256 threads (8 warps): warp handles one batch, lane-parallel
// rank scan + warp reduce.
__global__ void prep_kernel(const int* __restrict__ lens) {
    const int lane = threadIdx.x & 31;
    const int warp = threadIdx.x >> 5;
    const int b    = blockIdx.x * 8 + warp;
    const int len  = __ldg(&lens[b]);
    int rank = 0;
#pragma unroll
    for (int k = 0; k < 32; k++) {
        const int i  = k * 32 + lane;
        const int li = __ldg(&lens[i]);
        rank += (li > len) || ((li == len) && (i < b));
    }
    rank += __shfl_xor_sync(FULLM, rank, 16);
    rank += __shfl_xor_sync(FULLM, rank, 8);
    rank += __shfl_xor_sync(FULLM, rank, 4);
    rank += __shfl_xor_sync(FULLM, rank, 2);
    rank += __shfl_xor_sync(FULLM, rank, 1);
    if (lane == 0) g_order[rank] = b;
}

// ---------------- main CRF kernel ----------------------------------------
// 128 blocks x 256 threads (8 warps). Each warp owns ONE batch.
// Warps w and w+4 share SMSP (w&3): ranks r and 1023-r -> pair work ~513.
// Deep prefetch (distance 4, MLP=8) hides DRAM latency on the logits stream
// (R6 evidence: step time clamped to ~445cyc ~= DRAM latency at MLP~1).
__global__ __launch_bounds__(256, 1) void crf_kernel(
    const float* __restrict__ logits,   // [1024,512,50]
    const float* __restrict__ tr,       // [50,50]
    const int*   __restrict__ labels,   // [1024,512]
    const int*   __restrict__ lens)     // [1024]
{
    __shared__ __align__(16) float vbuf[8][2][64]; // [warp][dblbuf][state]

    const int lane = threadIdx.x & 31;
    const int warp = threadIdx.x >> 5;

    const int r  = blockIdx.x * 4 + (warp & 3);   // rank in [0,512)
    const int gw = (warp < 4) ? r : (1023 - r);   // this warp's rank
    const int b  = g_order[gw];
    const int len  = lens[b];
    const int base = b * 512;

    const int  j0 = 2 * lane;            // this lane owns states j0, j0+1
    const bool vl = (lane < 25);         // states 0..49 real; rest padding

    // ---- E = exp(transitions) rows for this lane's 2 states (regs) -----
    ull E0[25], E1[25];
#pragma unroll
    for (int k = 0; k < 25; k++) {
        float e00 = 0.f, e01 = 0.f, e10 = 0.f, e11 = 0.f;
        if (vl) {
            float2 r0 = *(const float2*)&tr[ j0      * 50 + 2 * k];
            float2 r1 = *(const float2*)&tr[(j0 + 1) * 50 + 2 * k];
            e00 = __expf(r0.x); e01 = __expf(r0.y);
            e10 = __expf(r1.x); e11 = __expf(r1.y);
        }
        E0[k] = pk2(e00, e01);
        E1[k] = pk2(e10, e11);
    }
    const float Es0 = vl ? __expf(tr[49 * 50 + j0])     : 0.f; // exp(tr[stop,j])
    const float Es1 = vl ? __expf(tr[49 * 50 + j0 + 1]) : 0.f;

    // ---- init v: onehot(start=48) in buffer 0 ---------------------------
    vbuf[warp][0][lane] = 0.f; vbuf[warp][0][lane + 32] = 0.f;
    vbuf[warp][1][lane] = 0.f; vbuf[warp][1][lane + 32] = 0.f;
    __syncwarp();
    if (lane == 24) vbuf[warp][0][48] = 1.f;
    __syncwarp();

    // ---- running state ---------------------------------------------------
    const float NEGBIG = -1e30f;
    float M = 0.f, logr = 0.f;           // logr = log(normalizer of prev step)
    float em = 0.f, trn = 0.f;
    int   prev = 48;
    float u0 = 0.f, u1 = 0.f;

    // ---- prefetch window: timesteps t..t+3 in registers ------------------
    float2 lgA[4]; int lbA[4];
#pragma unroll
    for (int s = 0; s < 4; s++) {
        const int tt = (s < len) ? s : (len - 1);
        lgA[s] = make_float2(NEGBIG, NEGBIG);
        if (vl) lgA[s] = *(const float2*)&logits[(base + tt) * 50 + j0];
        lbA[s] = __ldg(&labels[base + tt]);
    }

    for (int t0 = 0; t0 < len; t0 += 4) {
        // issue next window (t0+4 .. t0+7) first: 8 outstanding loads
        float2 lgN[4]; int lbN[4];
#pragma unroll
        for (int s = 0; s < 4; s++) {
            const int tq = t0 + 4 + s;
            const int tt = (tq < len) ? tq : (len - 1);
            lgN[s] = make_float2(NEGBIG, NEGBIG);
            if (vl) lgN[s] = *(const float2*)&logits[(base + tt) * 50 + j0];
            lbN[s] = __ldg(&labels[base + tt]);
        }

#pragma unroll
        for (int s = 0; s < 4; s++) {
            if (t0 + s < len) {                       // warp-uniform guard
                M += logr;                            // fold prev normalizer
                const float px = __expf(lgA[s].x - logr);
                const float py = __expf(lgA[s].y - logr);

                // emission + transition score gathers (off critical path)
                const int lab = lbA[s];
                const float cand = (lab & 1) ? lgA[s].y : lgA[s].x;
                em += __shfl_sync(FULLM, cand, lab >> 1);
                trn += __ldg(&tr[lab * 50 + prev]);
                prev = lab;

                // matvec: S_j = sum_i E[j,i]*v[i] (packed f32x2, 4 chains)
                const int cur = s & 1;                // == (t0+s)&1, t0%4==0
                const ulonglong2* vs = (const ulonglong2*)&vbuf[warp][cur][0];
                ull a0 = pk2(0.f, 0.f), b0 = a0, a1 = a0, b1 = a0;
#pragma unroll
                for (int k = 0; k < 12; k++) {
                    ulonglong2 vv = vs[k];
                    a0 = ffma2(E0[2 * k],     vv.x, a0);
                    b0 = ffma2(E0[2 * k + 1], vv.y, b0);
                    a1 = ffma2(E1[2 * k],     vv.x, a1);
                    b1 = ffma2(E1[2 * k + 1], vv.y, b1);
                }
                {   // tail pair: states 48,49
                    ull vt = *(const ull*)&vbuf[warp][cur][48];
                    a0 = ffma2(E0[24], vt, a0);
                    a1 = ffma2(E1[24], vt, a1);
                }
                float2 s0 = upk2(a0), s0b = upk2(b0), s1 = upk2(a1), s1b = upk2(b1);
                const float S0 = (s0.x + s0.y) + (s0b.x + s0b.y);
                const float S1 = (s1.x + s1.y) + (s1b.x + s1b.y);

                u0 = S0 * px;
                u1 = S1 * py;
                if (vl) *(float2*)&vbuf[warp][cur ^ 1][j0] = make_float2(u0, u1);

                // cheap normalizer: lane0 max broadcast (exact via M)
                float m = fmaxf(u0, u1);
                m = __shfl_sync(FULLM, m, 0);
                logr = __logf(m);
                __syncwarp();
            }
        }

#pragma unroll
        for (int s = 0; s < 4; s++) { lgA[s] = lgN[s]; lbA[s] = lbN[s]; }
    }

    // ---- finalize --------------------------------------------------------
    trn += __ldg(&tr[49 * 50 + prev]);
    float w = u0 * Es0 + u1 * Es1;
    w += __shfl_xor_sync(FULLM, w, 16);
    w += __shfl_xor_sync(FULLM, w, 8);
    w += __shfl_xor_sync(FULLM, w, 4);
    w += __shfl_xor_sync(FULLM, w, 2);
    w += __shfl_xor_sync(FULLM, w, 1);
    const float res = (M + __logf(w)) - em - trn;

    if (lane == 0) g_res[gw] = res;
}

// ---------------- deterministic final reduction ---------------------------
__global__ void reduce_kernel(float* __restrict__ out) {
    __shared__ float s[512];
    int i = threadIdx.x;
    s[i] = g_res[i] + g_res[i + 512];
    __syncthreads();
    for (int off = 256; off > 0; off >>= 1) {
        if (i < off) s[i] += s[i + off];
        __syncthreads();
    }
    if (i == 0) *out = s[0] * (1.0f / 1024.0f);
}

// ---------------- launch ---------------------------------------------------
extern "C" void kernel_launch(void* const* d_in, const int* in_sizes, int n_in,
                              void* d_out, int out_size) {
    const float* logits = (const float*)d_in[0];
    const float* trans  = (const float*)d_in[1];
    const int*   labels = (const int*)d_in[2];
    const int*   lens   = (const int*)d_in[3];
    float*       out    = (float*)d_out;

    prep_kernel<<<128, 256>>>(lens);
    crf_kernel<<<128, 256>>>(logits, trans, labels, lens);
    reduce_kernel<<<1, 512>>>(out);
}

// round 10
// speedup vs baseline: 1.7729x; 1.2113x over previous
#include <cuda_runtime.h>

typedef unsigned long long ull;
#define FULLM 0xffffffffu

// ---------------- device scratch (no allocations allowed) ----------------
__device__ int   g_order[1024];   // batch ids sorted by len descending
__device__ float g_res[1024];     // per-batch results (indexed by rank)

// ---------------- f32x2 helpers (sm_103a packed fp32 path) ---------------
__device__ __forceinline__ ull pk2(float lo, float hi) {
    ull r; asm("mov.b64 %0,{%1,%2};" : "=l"(r) : "f"(lo), "f"(hi)); return r;
}
__device__ __forceinline__ float2 upk2(ull v) {
    float2 f; asm("mov.b64 {%0,%1},%2;" : "=f"(f.x), "=f"(f.y) : "l"(v)); return f;
}
__device__ __forceinline__ ull ffma2(ull a, ull b, ull c) {
    ull d; asm("fma.rn.f32x2 %0,%1,%2,%3;" : "=l"(d) : "l"(a), "l"(b), "l"(c)); return d;
}

// ---------------- prep: rank batches by length (desc) --------------------
__global__ void prep_kernel(const int* __restrict__ lens) {
    const int lane = threadIdx.x & 31;
    const int warp = threadIdx.x >> 5;
    const int b    = blockIdx.x * 8 + warp;
    const int len  = __ldg(&lens[b]);
    int rank = 0;
#pragma unroll
    for (int k = 0; k < 32; k++) {
        const int i  = k * 32 + lane;
        const int li = __ldg(&lens[i]);
        rank += (li > len) || ((li == len) && (i < b));
    }
    rank += __shfl_xor_sync(FULLM, rank, 16);
    rank += __shfl_xor_sync(FULLM, rank, 8);
    rank += __shfl_xor_sync(FULLM, rank, 4);
    rank += __shfl_xor_sync(FULLM, rank, 2);
    rank += __shfl_xor_sync(FULLM, rank, 1);
    if (lane == 0) g_order[rank] = b;
}

// ---------------- main CRF kernel ----------------------------------------
// 128 blocks x 256 threads (8 warps), one batch per warp, ranks paired
// (r, 1023-r) per SMSP. R7 evidence: runtime == 512 * per-step serial chain.
// This version strips the chain to sync+LDS+depth7-FFMA+sum+mul+STS:
//  - normalizer = v[0] (from the LDS each lane already performs): log/exp
//    moved OFF the loop-carried cycle (exactness kept via running offset M)
//  - em gathered by per-lane predicate, reduced once at the end (no shfl/step)
//  - 8 accumulator chains -> FFMA2 depth 7 instead of 13
__global__ __launch_bounds__(256, 1) void crf_kernel(
    const float* __restrict__ logits,   // [1024,512,50]
    const float* __restrict__ tr,       // [50,50]
    const int*   __restrict__ labels,   // [1024,512]
    const int*   __restrict__ lens)     // [1024]
{
    __shared__ __align__(16) float vbuf[8][2][64]; // [warp][dblbuf][state]

    const int lane = threadIdx.x & 31;
    const int warp = threadIdx.x >> 5;

    const int r  = blockIdx.x * 4 + (warp & 3);   // rank in [0,512)
    const int gw = (warp < 4) ? r : (1023 - r);   // this warp's rank
    const int b  = g_order[gw];
    const int len  = lens[b];
    const int base = b * 512;

    const int  j0 = 2 * lane;            // this lane owns states j0, j0+1
    const bool vl = (lane < 25);         // states 0..49 real; rest padding

    // ---- E = exp(transitions) rows for this lane's 2 states (regs) -----
    ull E0[25], E1[25];
#pragma unroll
    for (int k = 0; k < 25; k++) {
        float e00 = 0.f, e01 = 0.f, e10 = 0.f, e11 = 0.f;
        if (vl) {
            float2 r0 = *(const float2*)&tr[ j0      * 50 + 2 * k];
            float2 r1 = *(const float2*)&tr[(j0 + 1) * 50 + 2 * k];
            e00 = __expf(r0.x); e01 = __expf(r0.y);
            e10 = __expf(r1.x); e11 = __expf(r1.y);
        }
        E0[k] = pk2(e00, e01);
        E1[k] = pk2(e10, e11);
    }
    const float Es0 = vl ? __expf(tr[49 * 50 + j0])     : 0.f; // exp(tr[stop,j])
    const float Es1 = vl ? __expf(tr[49 * 50 + j0 + 1]) : 0.f;

    // ---- init v: onehot(start=48) in buffer 0 ---------------------------
    vbuf[warp][0][lane] = 0.f; vbuf[warp][0][lane + 32] = 0.f;
    vbuf[warp][1][lane] = 0.f; vbuf[warp][1][lane + 32] = 0.f;
    __syncwarp();
    if (lane == 24) vbuf[warp][0][48] = 1.f;
    __syncwarp();

    // ---- running state ---------------------------------------------------
    const float NEGBIG = -1e30f;
    float M = 0.f;
    float em = 0.f, trn = 0.f;
    int   prev = 48;
    float u0 = 0.f, u1 = 0.f;

    // ---- prefetch window: timesteps t..t+3 in registers ------------------
    float2 lgA[4]; int lbA[4];
#pragma unroll
    for (int s = 0; s < 4; s++) {
        const int tt = (s < len) ? s : (len - 1);
        lgA[s] = make_float2(NEGBIG, NEGBIG);
        if (vl) lgA[s] = *(const float2*)&logits[(base + tt) * 50 + j0];
        lbA[s] = __ldg(&labels[base + tt]);
    }

    const ull z = pk2(0.f, 0.f);

    for (int t0 = 0; t0 < len; t0 += 4) {
        // issue next window (t0+4 .. t0+7): 8 outstanding loads
        float2 lgN[4]; int lbN[4];
#pragma unroll
        for (int s = 0; s < 4; s++) {
            const int tq = t0 + 4 + s;
            const int tt = (tq < len) ? tq : (len - 1);
            lgN[s] = make_float2(NEGBIG, NEGBIG);
            if (vl) lgN[s] = *(const float2*)&logits[(base + tt) * 50 + j0];
            lbN[s] = __ldg(&labels[base + tt]);
        }

#pragma unroll
        for (int s = 0; s < 4; s++) {
            if (t0 + s < len) {                       // warp-uniform guard
                const int cur = s & 1;                // == (t0+s)&1
                const ulonglong2* vs = (const ulonglong2*)&vbuf[warp][cur][0];

                // --- matvec: 8 accumulator chains, depth 7 ---------------
                ull A0 = z, A1 = z, A2 = z, A3 = z;
                ull B0 = z, B1 = z, B2 = z, B3 = z;
                float v0norm;
                {
                    ulonglong2 va = vs[0];
                    v0norm = upk2(va.x).x;            // v[0]: the normalizer
                    ulonglong2 vb = vs[1];
                    A0 = ffma2(E0[0], va.x, A0); A1 = ffma2(E0[1], va.y, A1);
                    A2 = ffma2(E0[2], vb.x, A2); A3 = ffma2(E0[3], vb.y, A3);
                    B0 = ffma2(E1[0], va.x, B0); B1 = ffma2(E1[1], va.y, B1);
                    B2 = ffma2(E1[2], vb.x, B2); B3 = ffma2(E1[3], vb.y, B3);
                }
#pragma unroll
                for (int k = 4; k < 24; k += 4) {
                    ulonglong2 va = vs[k >> 1];
                    ulonglong2 vb = vs[(k >> 1) + 1];
                    A0 = ffma2(E0[k],     va.x, A0); A1 = ffma2(E0[k + 1], va.y, A1);
                    A2 = ffma2(E0[k + 2], vb.x, A2); A3 = ffma2(E0[k + 3], vb.y, A3);
                    B0 = ffma2(E1[k],     va.x, B0); B1 = ffma2(E1[k + 1], va.y, B1);
                    B2 = ffma2(E1[k + 2], vb.x, B2); B3 = ffma2(E1[k + 3], vb.y, B3);
                }
                {   // tail: pair 24 (states 48,49)
                    ull vt = vs[12].x;
                    A0 = ffma2(E0[24], vt, A0);
                    B0 = ffma2(E1[24], vt, B0);
                }

                // --- off-chain: normalizer + exp of logits ----------------
                // logr/log + exp run in parallel with the FFMA chain above.
                const float logr = (t0 + s > 0) ? __logf(v0norm) : 0.f;
                M += logr;
                const float px = __expf(lgA[s].x - logr);
                const float py = __expf(lgA[s].y - logr);

                // emission: predicated per-lane accumulate (no shfl)
                const int lab = lbA[s];
                if ((lab >> 1) == lane) em += (lab & 1) ? lgA[s].y : lgA[s].x;
                trn += __ldg(&tr[lab * 50 + prev]);
                prev = lab;

                // --- finish matvec: sum 8 chains --------------------------
                float2 a0 = upk2(A0), a1 = upk2(A1), a2 = upk2(A2), a3 = upk2(A3);
                float2 b0 = upk2(B0), b1 = upk2(B1), b2 = upk2(B2), b3 = upk2(B3);
                const float S0 = ((a0.x + a0.y) + (a1.x + a1.y))
                               + ((a2.x + a2.y) + (a3.x + a3.y));
                const float S1 = ((b0.x + b0.y) + (b1.x + b1.y))
                               + ((b2.x + b2.y) + (b3.x + b3.y));

                u0 = S0 * px;
                u1 = S1 * py;
                if (vl) *(float2*)&vbuf[warp][cur ^ 1][j0] = make_float2(u0, u1);
                __syncwarp();
            }
        }

#pragma unroll
        for (int s = 0; s < 4; s++) { lgA[s] = lgN[s]; lbA[s] = lbN[s]; }
    }

    // ---- finalize --------------------------------------------------------
    trn += __ldg(&tr[49 * 50 + prev]);
    float w = u0 * Es0 + u1 * Es1;
    w  += __shfl_xor_sync(FULLM, w, 16);
    em += __shfl_xor_sync(FULLM, em, 16);
    w  += __shfl_xor_sync(FULLM, w, 8);
    em += __shfl_xor_sync(FULLM, em, 8);
    w  += __shfl_xor_sync(FULLM, w, 4);
    em += __shfl_xor_sync(FULLM, em, 4);
    w  += __shfl_xor_sync(FULLM, w, 2);
    em += __shfl_xor_sync(FULLM, em, 2);
    w  += __shfl_xor_sync(FULLM, w, 1);
    em += __shfl_xor_sync(FULLM, em, 1);
    const float res = (M + __logf(w)) - em - trn;

    if (lane == 0) g_res[gw] = res;
}

// ---------------- deterministic final reduction ---------------------------
__global__ void reduce_kernel(float* __restrict__ out) {
    __shared__ float s[512];
    int i = threadIdx.x;
    s[i] = g_res[i] + g_res[i + 512];
    __syncthreads();
    for (int off = 256; off > 0; off >>= 1) {
        if (i < off) s[i] += s[i + off];
        __syncthreads();
    }
    if (i == 0) *out = s[0] * (1.0f / 1024.0f);
}

// ---------------- launch ---------------------------------------------------
extern "C" void kernel_launch(void* const* d_in, const int* in_sizes, int n_in,
                              void* d_out, int out_size) {
    const float* logits = (const float*)d_in[0];
    const float* trans  = (const float*)d_in[1];
    const int*   labels = (const int*)d_in[2];
    const int*   lens   = (const int*)d_in[3];
    float*       out    = (float*)d_out;

    prep_kernel<<<128, 256>>>(lens);
    crf_kernel<<<128, 256>>>(logits, trans, labels, lens);
    reduce_kernel<<<1, 512>>>(out);
}

// round 11
// speedup vs baseline: 1.8981x; 1.0706x over previous
#include <cuda_runtime.h>

typedef unsigned long long ull;
#define FULLM 0xffffffffu

// ---------------- device scratch (no allocations allowed) ----------------
__device__ int   g_order[1024];   // batch ids sorted by len descending
__device__ float g_res[1024];     // per-batch results (indexed by rank)
__device__ int   g_done;          // completed-block counter (reset by prep)

// ---------------- f32x2 helpers (sm_103a packed fp32 path) ---------------
__device__ __forceinline__ ull pk2(float lo, float hi) {
    ull r; asm("mov.b64 %0,{%1,%2};" : "=l"(r) : "f"(lo), "f"(hi)); return r;
}
__device__ __forceinline__ float2 upk2(ull v) {
    float2 f; asm("mov.b64 {%0,%1},%2;" : "=f"(f.x), "=f"(f.y) : "l"(v)); return f;
}
__device__ __forceinline__ ull ffma2(ull a, ull b, ull c) {
    ull d; asm("fma.rn.f32x2 %0,%1,%2,%3;" : "=l"(d) : "l"(a), "l"(b), "l"(c)); return d;
}

// ---------------- prep: rank batches by length (desc) --------------------
__global__ void prep_kernel(const int* __restrict__ lens) {
    if (blockIdx.x == 0 && threadIdx.x == 0) g_done = 0;   // reset reducer
    const int lane = threadIdx.x & 31;
    const int warp = threadIdx.x >> 5;
    const int b    = blockIdx.x * 8 + warp;
    const int len  = __ldg(&lens[b]);
    int rank = 0;
#pragma unroll
    for (int k = 0; k < 32; k++) {
        const int i  = k * 32 + lane;
        const int li = __ldg(&lens[i]);
        rank += (li > len) || ((li == len) && (i < b));
    }
    rank += __shfl_xor_sync(FULLM, rank, 16);
    rank += __shfl_xor_sync(FULLM, rank, 8);
    rank += __shfl_xor_sync(FULLM, rank, 4);
    rank += __shfl_xor_sync(FULLM, rank, 2);
    rank += __shfl_xor_sync(FULLM, rank, 1);
    if (lane == 0) g_order[rank] = b;
}

// ---------------- main CRF kernel ----------------------------------------
// 128 blocks x 256 threads, one batch/warp, ranks (r, 1023-r) per SMSP.
// R10 evidence: wall == len_max * per-step chain (~290cyc); the ~140cyc gap
// vs the dataflow model is attributed to BSSY/BSYNC envelopes from 3
// unproven-uniform branches per step. This version is BRANCH-FREE in the
// step body: exact-trip unrolled loop, predicated em, unguarded clamped
// loads, unguarded stores (padding lanes write zeros). Reduction folded in
// (last-block pattern) -> 2 launches total.
__global__ __launch_bounds__(256, 1) void crf_kernel(
    const float* __restrict__ logits,   // [1024,512,50]
    const float* __restrict__ tr,       // [50,50]
    const int*   __restrict__ labels,   // [1024,512]
    const int*   __restrict__ lens,     // [1024]
    float*       __restrict__ out)      // [1]
{
    __shared__ __align__(16) float vbuf[8][2][64]; // [warp][dblbuf][state]
    __shared__ float red[256];
    __shared__ int   sflag;

    const int lane = threadIdx.x & 31;
    const int warp = threadIdx.x >> 5;

    const int r  = blockIdx.x * 4 + (warp & 3);   // rank in [0,512)
    const int gw = (warp < 4) ? r : (1023 - r);   // this warp's rank
    const int b  = g_order[gw];
    const int len  = lens[b];
    const int base = b * 512;

    const int  j0  = 2 * lane;           // this lane owns states j0, j0+1
    const bool vl  = (lane < 25);        // states 0..49 real; rest padding
    const int  j0c = vl ? j0 : 0;        // clamped column for unguarded loads

    // ---- E = exp(transitions) rows for this lane's 2 states (regs) -----
    ull E0[25], E1[25];
#pragma unroll
    for (int k = 0; k < 25; k++) {
        float e00 = 0.f, e01 = 0.f, e10 = 0.f, e11 = 0.f;
        if (vl) {
            float2 r0 = *(const float2*)&tr[ j0      * 50 + 2 * k];
            float2 r1 = *(const float2*)&tr[(j0 + 1) * 50 + 2 * k];
            e00 = __expf(r0.x); e01 = __expf(r0.y);
            e10 = __expf(r1.x); e11 = __expf(r1.y);
        }
        E0[k] = pk2(e00, e01);
        E1[k] = pk2(e10, e11);
    }
    const float Es0 = vl ? __expf(tr[49 * 50 + j0])     : 0.f; // exp(tr[stop,j])
    const float Es1 = vl ? __expf(tr[49 * 50 + j0 + 1]) : 0.f;

    // ---- init v: onehot(start=48) in buffer 0 ---------------------------
    vbuf[warp][0][lane] = 0.f; vbuf[warp][0][lane + 32] = 0.f;
    vbuf[warp][1][lane] = 0.f; vbuf[warp][1][lane + 32] = 0.f;
    __syncwarp();
    if (lane == 24) vbuf[warp][0][48] = 1.f;
    __syncwarp();

    // ---- running state ---------------------------------------------------
    float M = 0.f;
    float em = 0.f, trn = 0.f;
    int   prev = 48;
    float u0 = 0.f, u1 = 0.f;

    // ---- rotating prefetch queue: slots t&3, distance 4 ------------------
    float2 lgq[4]; int lbq[4];
#pragma unroll
    for (int s = 0; s < 4; s++) {
        const int tt = (s < len) ? s : (len - 1);
        lgq[s] = *(const float2*)&logits[(base + tt) * 50 + j0c];
        lbq[s] = __ldg(&labels[base + tt]);
    }

    const ull z = pk2(0.f, 0.f);

    // one branch-free forward step; q/cur are literal in the main loop
    auto step = [&](int t, int q, int cur) {
        const ulonglong2* vs = (const ulonglong2*)&vbuf[warp][cur][0];

        // matvec: 8 accumulator chains
        ull A0 = z, A1 = z, A2 = z, A3 = z;
        ull B0 = z, B1 = z, B2 = z, B3 = z;
        float v0norm;
        {
            ulonglong2 va = vs[0];
            v0norm = upk2(va.x).x;            // v[0]: the normalizer
            ulonglong2 vb = vs[1];
            A0 = ffma2(E0[0], va.x, A0); A1 = ffma2(E0[1], va.y, A1);
            A2 = ffma2(E0[2], vb.x, A2); A3 = ffma2(E0[3], vb.y, A3);
            B0 = ffma2(E1[0], va.x, B0); B1 = ffma2(E1[1], va.y, B1);
            B2 = ffma2(E1[2], vb.x, B2); B3 = ffma2(E1[3], vb.y, B3);
        }
#pragma unroll
        for (int k = 4; k < 24; k += 4) {
            ulonglong2 va = vs[k >> 1];
            ulonglong2 vb = vs[(k >> 1) + 1];
            A0 = ffma2(E0[k],     va.x, A0); A1 = ffma2(E0[k + 1], va.y, A1);
            A2 = ffma2(E0[k + 2], vb.x, A2); A3 = ffma2(E0[k + 3], vb.y, A3);
            B0 = ffma2(E1[k],     va.x, B0); B1 = ffma2(E1[k + 1], va.y, B1);
            B2 = ffma2(E1[k + 2], vb.x, B2); B3 = ffma2(E1[k + 3], vb.y, B3);
        }
        {   // tail: pair 24 (states 48,49)
            ull vt = vs[12].x;
            A0 = ffma2(E0[24], vt, A0);
            B0 = ffma2(E1[24], vt, B0);
        }

        // off-chain scalar work (overlaps the FFMA chain)
        const float logr = (t > 0) ? __logf(v0norm) : 0.f;   // SEL, no branch
        M += logr;
        const float2 lg = lgq[q];
        const int   lab = lbq[q];
        const float px = __expf(lg.x - logr);
        const float py = __expf(lg.y - logr);
        em += ((lab >> 1) == lane) ? ((lab & 1) ? lg.y : lg.x) : 0.f; // FSEL
        trn += __ldg(&tr[lab * 50 + prev]);
        prev = lab;

        // prefetch t+4 into the slot just consumed (clamped, unguarded)
        const int tq = t + 4;
        const int tt = (tq < len) ? tq : (len - 1);
        lgq[q] = *(const float2*)&logits[(base + tt) * 50 + j0c];
        lbq[q] = __ldg(&labels[base + tt]);

        // finish matvec: sum 8 chains
        float2 a0 = upk2(A0), a1 = upk2(A1), a2 = upk2(A2), a3 = upk2(A3);
        float2 b0 = upk2(B0), b1 = upk2(B1), b2 = upk2(B2), b3 = upk2(B3);
        const float S0 = ((a0.x + a0.y) + (a1.x + a1.y))
                       + ((a2.x + a2.y) + (a3.x + a3.y));
        const float S1 = ((b0.x + b0.y) + (b1.x + b1.y))
                       + ((b2.x + b2.y) + (b3.x + b3.y));

        u0 = S0 * px;                      // lanes 25..31: S=0 -> u=0
        u1 = S1 * py;
        *(float2*)&vbuf[warp][cur ^ 1][j0] = make_float2(u0, u1); // all lanes
        __syncwarp();
    };

    const int len4 = len & ~3;
    for (int t0 = 0; t0 < len4; t0 += 4) {   // exact-trip, no step guard
        step(t0 + 0, 0, 0);
        step(t0 + 1, 1, 1);
        step(t0 + 2, 2, 0);
        step(t0 + 3, 3, 1);
    }
    for (int t = len4; t < len; t++)          // <=3 steps; data already queued
        step(t, t & 3, t & 1);

    // ---- finalize --------------------------------------------------------
    trn += __ldg(&tr[49 * 50 + prev]);
    float w = u0 * Es0 + u1 * Es1;
    w  += __shfl_xor_sync(FULLM, w, 16);
    em += __shfl_xor_sync(FULLM, em, 16);
    w  += __shfl_xor_sync(FULLM, w, 8);
    em += __shfl_xor_sync(FULLM, em, 8);
    w  += __shfl_xor_sync(FULLM, w, 4);
    em += __shfl_xor_sync(FULLM, em, 4);
    w  += __shfl_xor_sync(FULLM, w, 2);
    em += __shfl_xor_sync(FULLM, em, 2);
    w  += __shfl_xor_sync(FULLM, w, 1);
    em += __shfl_xor_sync(FULLM, em, 1);
    const float res = (M + __logf(w)) - em - trn;

    if (lane == 0) g_res[gw] = res;

    // ---- last-block deterministic reduction ------------------------------
    __syncthreads();
    if (threadIdx.x == 0) {
        __threadfence();
        const int p = atomicAdd(&g_done, 1);
        sflag = (p == (int)gridDim.x - 1);
    }
    __syncthreads();
    if (sflag) {
        const int i = threadIdx.x;
        red[i] = (g_res[i] + g_res[i + 256]) + (g_res[i + 512] + g_res[i + 768]);
        __syncthreads();
        for (int off = 128; off > 0; off >>= 1) {
            if (i < off) red[i] += red[i + off];
            __syncthreads();
        }
        if (i == 0) *out = red[0] * (1.0f / 1024.0f);
    }
}

// ---------------- launch ---------------------------------------------------
extern "C" void kernel_launch(void* const* d_in, const int* in_sizes, int n_in,
                              void* d_out, int out_size) {
    const float* logits = (const float*)d_in[0];
    const float* trans  = (const float*)d_in[1];
    const int*   labels = (const int*)d_in[2];
    const int*   lens   = (const int*)d_in[3];
    float*       out    = (float*)d_out;

    prep_kernel<<<128, 256>>>(lens);
    crf_kernel<<<128, 256>>>(logits, trans, labels, lens, out);
}